// round 2
// baseline (speedup 1.0000x reference)
#include <cuda_runtime.h>
#include <cstdint>
#include <cstddef>

// ---------------- problem constants ----------------
#define N_TEXT   90000
#define N_NODES  100000
#define EMBD     256
#define NRELS    500
#define FEAT     266          // 256 emb + 2 topic + 2*2 fwd + 2*2 rev
#define FEAT_PAD 272          // padded, zero-filled, multiple of 8
#define W1LD     1056         // 1044 padded to mult of 8 (pad zeroed)
#define NSAMP    5
#define JROWS    (NSAMP*256)  // 1280 stacked hidden rows
#define W1SZ     (256*1044)   // 267264 noise elements per sample

// ---------------- device scratch (static, no allocs) ----------------
__device__ float g_W1[JROWS * W1LD];               // 5.4 MB  stacked sampled w1
__device__ float g_b1[JROWS];
__device__ float g_w2[JROWS];
__device__ float g_b2[NSAMP];
__device__ float g_cvec[JROWS];                    // b1 + W_q @ q
__device__ float g_hE[(size_t)N_NODES * FEAT_PAD]; // 108.8 MB node features
__device__ float g_A[NRELS * JROWS];               // 2.56 MB relation part
__device__ float g_B[(size_t)N_NODES * JROWS];     // 512 MB  head part
__device__ float g_C[(size_t)N_NODES * JROWS];     // 512 MB  tail part
__device__ float g_degT[N_NODES];
__device__ float g_degH[N_NODES];
__device__ float g_f1[N_NODES*2], g_f2[N_NODES*2];
__device__ float g_r1[N_NODES*2], g_r2[N_NODES*2];
__device__ int   g_is64;

// ---------------- index dtype shim ----------------
__global__ void k_detect(const unsigned int* p) {
    // int64 values < 2^31 -> every odd 32-bit word is 0
    int nz = 0;
    for (int j = 1; j < 256; j += 2) nz |= (p[j] != 0u);
    g_is64 = nz ? 0 : 1;
}
__device__ __forceinline__ int getid(const void* p, int e) {
    if (g_is64) return (int)((const long long*)p)[e];
    return ((const int*)p)[e];
}

// ---------------- JAX threefry2x32 (20 rounds) ----------------
__device__ __forceinline__ unsigned rotl32(unsigned v, int r) {
    return (v << r) | (v >> (32 - r));
}
__device__ __forceinline__ void tf2x32(unsigned k0, unsigned k1,
                                       unsigned& x0, unsigned& x1) {
    unsigned ks0 = k0, ks1 = k1, ks2 = k0 ^ k1 ^ 0x1BD11BDAu;
    x0 += ks0; x1 += ks1;
    const int RA[4] = {13, 15, 26, 6};
    const int RB[4] = {17, 29, 16, 24};
    unsigned ks[3] = {ks0, ks1, ks2};
    #pragma unroll
    for (int i = 0; i < 5; i++) {
        const int* R = (i & 1) ? RB : RA;
        #pragma unroll
        for (int j = 0; j < 4; j++) {
            x0 += x1; x1 = rotl32(x1, R[j]); x1 ^= x0;
        }
        x0 += ks[(i + 1) % 3];
        x1 += ks[(i + 2) % 3] + (unsigned)(i + 1);
    }
}
// === jax_threefry_partitionable=True (modern JAX default) semantics ===
// fold_in(key42,(i)): folded = enc_{(0,42)}(0, i)            (same in both modes)
// split(folded, 4):   sk[m]  = enc_{folded}(0, m)  -> (x0, x1) is the new key
// random_bits 32-bit: bits[j] = x0 ^ x1 of enc_{sk}(0, j)
__device__ __forceinline__ void sample_keys(int i, unsigned sk[4][2]) {
    unsigned a = 0u, b = (unsigned)i;
    tf2x32(0u, 42u, a, b);                       // fold_in
    #pragma unroll
    for (int m = 0; m < 4; m++) {
        unsigned x0 = 0u, x1 = (unsigned)m;
        tf2x32(a, b, x0, x1);
        sk[m][0] = x0; sk[m][1] = x1;
    }
}
__device__ __forceinline__ unsigned draw_bits(unsigned k0, unsigned k1, unsigned j) {
    unsigned x0 = 0u, x1 = j;
    tf2x32(k0, k1, x0, x1);
    return x0 ^ x1;
}
__device__ __forceinline__ float jax_normal(unsigned bits) {
    float f = __uint_as_float(0x3F800000u | (bits >> 9)) - 1.0f; // [0,1)
    const float lo = -0.99999994f;  // nextafterf(-1,0)
    float u = f * 2.0f + lo;        // (1.0 - lo) rounds to 2.0f, as in XLA
    u = fmaxf(lo, u);
    return 1.4142135623730951f * erfinvf(u);
}
__device__ __forceinline__ float softplus_f(float x) {
    return fmaxf(x, 0.0f) + log1pf(expf(-fabsf(x)));  // logaddexp(x,0)
}

// ---------------- weight sampling ----------------
__global__ void k_gen_w1(const float* __restrict__ mu,
                         const float* __restrict__ rho) {
    int tid = blockIdx.x * blockDim.x + threadIdx.x;
    if (tid >= NSAMP * W1SZ) return;
    int i = tid / W1SZ, j = tid % W1SZ;
    unsigned sk[4][2]; sample_keys(i, sk);
    unsigned bits = draw_bits(sk[0][0], sk[0][1], (unsigned)j);
    float eps = jax_normal(bits);
    int row = j / 1044, k = j % 1044;
    g_W1[(size_t)(i * 256 + row) * W1LD + k] = mu[j] + eps * softplus_f(rho[j]);
}
__global__ void k_gen_small(const float* __restrict__ b1mu, const float* __restrict__ b1rho,
                            const float* __restrict__ w2mu, const float* __restrict__ w2rho,
                            const float* __restrict__ b2mu, const float* __restrict__ b2rho) {
    int tid = blockIdx.x * blockDim.x + threadIdx.x;
    if (tid >= NSAMP * 513) return;
    int i = tid / 513, m = tid % 513;
    unsigned sk[4][2]; sample_keys(i, sk);
    if (m < 256) {                       // b1 ~ normal(sk1, (256,))
        unsigned bits = draw_bits(sk[1][0], sk[1][1], (unsigned)m);
        g_b1[i * 256 + m] = b1mu[m] + jax_normal(bits) * softplus_f(b1rho[m]);
    } else if (m < 512) {                // w2 ~ normal(sk2, (1,256))
        int j = m - 256;
        unsigned bits = draw_bits(sk[2][0], sk[2][1], (unsigned)j);
        g_w2[i * 256 + j] = w2mu[j] + jax_normal(bits) * softplus_f(w2rho[j]);
    } else {                             // b2 ~ normal(sk3, (1,))
        unsigned bits = draw_bits(sk[3][0], sk[3][1], 0u);
        g_b2[i] = b2mu[0] + jax_normal(bits) * softplus_f(b2rho[0]);
    }
}

// ---------------- zero scratch used by atomics + pads ----------------
__global__ void k_zero() {
    int tid = blockIdx.x * blockDim.x + threadIdx.x;
    int stride = gridDim.x * blockDim.x;
    for (int i = tid; i < N_NODES; i += stride) { g_degT[i] = 0.f; g_degH[i] = 0.f; }
    for (int i = tid; i < N_NODES * 2; i += stride) {
        g_f1[i] = 0.f; g_f2[i] = 0.f; g_r1[i] = 0.f; g_r2[i] = 0.f;
    }
    for (int i = tid; i < JROWS * (W1LD - 1044); i += stride) {
        int j = i / (W1LD - 1044), k = 1044 + i % (W1LD - 1044);
        g_W1[(size_t)j * W1LD + k] = 0.f;   // zero W1 pad cols
    }
}

// ---------------- DDE mean-conv ----------------
__global__ void k_deg(const void* hid, const void* tid_, int E) {
    int e = blockIdx.x * blockDim.x + threadIdx.x;
    if (e >= E) return;
    atomicAdd(&g_degT[getid(tid_, e)], 1.0f);
    atomicAdd(&g_degH[getid(hid, e)], 1.0f);
}
// xsel: -1 = external (topic), 0 = g_f1, 1 = g_r1 ; accsel: 0..3 -> f1,f2,r1,r2
__global__ void k_scatter(const void* sids, const void* dids,
                          const float* __restrict__ xext, int xsel, int accsel, int E) {
    int e = blockIdx.x * blockDim.x + threadIdx.x;
    if (e >= E) return;
    const float* x = (xsel < 0) ? xext : (xsel == 0 ? g_f1 : g_r1);
    float* acc = (accsel == 0) ? g_f1 : (accsel == 1) ? g_f2
               : (accsel == 2) ? g_r1 : g_r2;
    int s = getid(sids, e), d = getid(dids, e);
    atomicAdd(&acc[2 * d],     x[2 * s]);
    atomicAdd(&acc[2 * d + 1], x[2 * s + 1]);
}
__global__ void k_div(int accsel, int degsel) {
    int v = blockIdx.x * blockDim.x + threadIdx.x;
    if (v >= N_NODES) return;
    float* acc = (accsel == 0) ? g_f1 : (accsel == 1) ? g_f2
               : (accsel == 2) ? g_r1 : g_r2;
    float d = fmaxf(degsel == 0 ? g_degT[v] : g_degH[v], 1.0f);
    acc[2 * v]     /= d;
    acc[2 * v + 1] /= d;
}

// ---------------- build node feature matrix ----------------
__global__ void k_pack(const float* __restrict__ ent, const float* __restrict__ nte,
                       const float* __restrict__ topic) {
    long long tid = (long long)blockIdx.x * blockDim.x + threadIdx.x;
    if (tid >= (long long)N_NODES * FEAT_PAD) return;
    int v = (int)(tid / FEAT_PAD), c = (int)(tid % FEAT_PAD);
    float val;
    if (c < 256)      val = (v < N_TEXT) ? ent[(size_t)v * 256 + c] : nte[c];
    else if (c < 258) val = topic[v * 2 + (c - 256)];
    else if (c < 260) val = g_f1[v * 2 + (c - 258)];
    else if (c < 262) val = g_f2[v * 2 + (c - 260)];
    else if (c < 264) val = g_r1[v * 2 + (c - 262)];
    else if (c < 266) val = g_r2[v * 2 + (c - 264)];
    else              val = 0.0f;
    g_hE[(size_t)v * FEAT_PAD + c] = val;
}

// ---------------- cvec = b1 + W1[:, :256] @ q ----------------
__global__ void k_cvec(const float* __restrict__ q) {
    int w = (blockIdx.x * blockDim.x + threadIdx.x) >> 5;
    int lane = threadIdx.x & 31;
    if (w >= JROWS) return;
    float s = 0.f;
    for (int k = lane; k < 256; k += 32) s += g_W1[(size_t)w * W1LD + k] * q[k];
    #pragma unroll
    for (int o = 16; o; o >>= 1) s += __shfl_xor_sync(0xFFFFFFFFu, s, o);
    if (!lane) g_cvec[w] = s + g_b1[w];
}

// ---------------- SGEMM: out[M,1280] = X[M,K] @ W1[:, off:off+K]^T ----------------
// xsel: 0 = Xext, 1 = g_hE ;  osel: 0 = g_A, 1 = g_B, 2 = g_C
__global__ void __launch_bounds__(256)
k_sgemm(const float* __restrict__ Xext, int xsel, int ldx, int M, int K, int off, int osel) {
    __shared__ float As[8][128];
    __shared__ float Bs[8][128];
    const float* X = (xsel == 0) ? Xext : g_hE;
    float* out = (osel == 0) ? g_A : (osel == 1) ? g_B : g_C;

    int m0 = blockIdx.y * 128, n0 = blockIdx.x * 128;
    int tid = threadIdx.x;
    int lr = tid >> 1, lk = (tid & 1) * 4;   // loader: row 0..127, k 0/4
    int tr = tid >> 4, tc = tid & 15;        // 16x16 thread grid, 8x8 micro
    const float* Wp = g_W1 + (size_t)n0 * W1LD + off;

    float acc[8][8];
    #pragma unroll
    for (int i = 0; i < 8; i++)
        #pragma unroll
        for (int j = 0; j < 8; j++) acc[i][j] = 0.f;

    for (int k0 = 0; k0 < K; k0 += 8) {
        #pragma unroll
        for (int u = 0; u < 4; u++) {
            int m = m0 + lr;
            As[lk + u][lr] = (m < M) ? X[(size_t)m * ldx + k0 + lk + u] : 0.f;
            Bs[lk + u][lr] = Wp[(size_t)lr * W1LD + k0 + lk + u];
        }
        __syncthreads();
        #pragma unroll
        for (int kk = 0; kk < 8; kk++) {
            float4 a0 = *(const float4*)&As[kk][tr * 8];
            float4 a1 = *(const float4*)&As[kk][tr * 8 + 4];
            float4 b0 = *(const float4*)&Bs[kk][tc * 8];
            float4 b1 = *(const float4*)&Bs[kk][tc * 8 + 4];
            float a[8] = {a0.x, a0.y, a0.z, a0.w, a1.x, a1.y, a1.z, a1.w};
            float b[8] = {b0.x, b0.y, b0.z, b0.w, b1.x, b1.y, b1.z, b1.w};
            #pragma unroll
            for (int i = 0; i < 8; i++)
                #pragma unroll
                for (int j = 0; j < 8; j++) acc[i][j] += a[i] * b[j];
        }
        __syncthreads();
    }
    #pragma unroll
    for (int i = 0; i < 8; i++) {
        int m = m0 + tr * 8 + i;
        if (m < M) {
            float4* dst = (float4*)&out[(size_t)m * JROWS + n0 + tc * 8];
            dst[0] = make_float4(acc[i][0], acc[i][1], acc[i][2], acc[i][3]);
            dst[1] = make_float4(acc[i][4], acc[i][5], acc[i][6], acc[i][7]);
        }
    }
}

// ---------------- per-edge: gather + relu + dot(w2), mean over samples ----------------
__global__ void __launch_bounds__(256)
k_edge(const void* hid, const void* rid, const void* tid_,
       float* __restrict__ out, int E) {
    int gw = (blockIdx.x * blockDim.x + threadIdx.x) >> 5;
    int lane = threadIdx.x & 31;
    if (gw >= E) return;
    int h = getid(hid, gw), t = getid(tid_, gw), r = getid(rid, gw);
    const float4* Bp = (const float4*)(g_B + (size_t)h * JROWS);
    const float4* Cp = (const float4*)(g_C + (size_t)t * JROWS);
    const float4* Ap = (const float4*)(g_A + (size_t)r * JROWS);
    const float4* cp = (const float4*)g_cvec;
    const float4* wp = (const float4*)g_w2;
    float acc = 0.f;
    #pragma unroll
    for (int it = 0; it < 10; it++) {
        int idx = it * 32 + lane;
        float4 b = Bp[idx], c = Cp[idx], a = Ap[idx], cc = cp[idx], w = wp[idx];
        acc += fmaxf(b.x + c.x + a.x + cc.x, 0.f) * w.x;
        acc += fmaxf(b.y + c.y + a.y + cc.y, 0.f) * w.y;
        acc += fmaxf(b.z + c.z + a.z + cc.z, 0.f) * w.z;
        acc += fmaxf(b.w + c.w + a.w + cc.w, 0.f) * w.w;
    }
    #pragma unroll
    for (int o = 16; o; o >>= 1) acc += __shfl_xor_sync(0xFFFFFFFFu, acc, o);
    if (!lane) {
        float b2s = g_b2[0] + g_b2[1] + g_b2[2] + g_b2[3] + g_b2[4];
        out[gw] = (acc + b2s) / 5.0f;
    }
}

// ---------------- host launch ----------------
extern "C" void kernel_launch(void* const* d_in, const int* in_sizes, int n_in,
                              void* d_out, int out_size) {
    // num_non_text_entities may or may not be materialized as input #5
    int base = (n_in >= 7 && in_sizes[5] == 1) ? 1 : 0;
    const void*  hid   = d_in[0];
    const void*  rid   = d_in[1];
    const void*  tidp  = d_in[2];
    const float* q     = (const float*)d_in[3];
    const float* ent   = (const float*)d_in[4];
    const float* rel   = (const float*)d_in[5 + base];
    const float* topic = (const float*)d_in[6 + base];
    const float* nte   = (const float*)d_in[7 + base];
    const float* w1mu  = (const float*)d_in[8 + base];
    const float* w1rho = (const float*)d_in[9 + base];
    const float* b1mu  = (const float*)d_in[10 + base];
    const float* b1rho = (const float*)d_in[11 + base];
    const float* w2mu  = (const float*)d_in[12 + base];
    const float* w2rho = (const float*)d_in[13 + base];
    const float* b2mu  = (const float*)d_in[14 + base];
    const float* b2rho = (const float*)d_in[15 + base];
    int E = in_sizes[0];
    float* out = (float*)d_out;

    k_detect<<<1, 1>>>((const unsigned int*)hid);
    k_zero<<<1024, 256>>>();
    k_gen_w1<<<(NSAMP * W1SZ + 255) / 256, 256>>>(w1mu, w1rho);
    k_gen_small<<<(NSAMP * 513 + 255) / 256, 256>>>(b1mu, b1rho, w2mu, w2rho, b2mu, b2rho);

    int eb = (E + 255) / 256;
    k_deg<<<eb, 256>>>(hid, tidp, E);
    // forward rounds (h -> t, divide by in-deg via t)
    k_scatter<<<eb, 256>>>(hid, tidp, topic, -1, 0, E);
    k_div<<<(N_NODES + 255) / 256, 256>>>(0, 0);
    k_scatter<<<eb, 256>>>(hid, tidp, nullptr, 0, 1, E);
    k_div<<<(N_NODES + 255) / 256, 256>>>(1, 0);
    // reverse rounds (t -> h)
    k_scatter<<<eb, 256>>>(tidp, hid, topic, -1, 2, E);
    k_div<<<(N_NODES + 255) / 256, 256>>>(2, 1);
    k_scatter<<<eb, 256>>>(tidp, hid, nullptr, 1, 3, E);
    k_div<<<(N_NODES + 255) / 256, 256>>>(3, 1);

    long long packN = (long long)N_NODES * FEAT_PAD;
    k_pack<<<(unsigned)((packN + 255) / 256), 256>>>(ent, nte, topic);
    k_cvec<<<(JROWS * 32) / 256, 256>>>(q);

    // A = rel @ W1[:,522:778]^T   (K=256)
    k_sgemm<<<dim3(10, (NRELS + 127) / 128), 256>>>(rel, 0, 256, NRELS, 256, 522, 0);
    // B = hE @ W1[:,256:...]^T    (K=272 padded; extra cols hit zero features)
    k_sgemm<<<dim3(10, (N_NODES + 127) / 128), 256>>>(nullptr, 1, FEAT_PAD, N_NODES, FEAT_PAD, 256, 1);
    // C = hE @ W1[:,778:...]^T    (cols 1044..1049 are zero pad in W1)
    k_sgemm<<<dim3(10, (N_NODES + 127) / 128), 256>>>(nullptr, 1, FEAT_PAD, N_NODES, FEAT_PAD, 778, 2);

    long long tot = (long long)E * 32;
    k_edge<<<(unsigned)((tot + 255) / 256), 256>>>(hid, rid, tidp, out, E);
}

// round 3
// speedup vs baseline: 1.9937x; 1.9937x over previous
#include <cuda_runtime.h>
#include <cuda_bf16.h>
#include <cstdint>
#include <cstddef>

// ---------------- problem constants ----------------
#define N_TEXT   90000
#define N_NODES  100000
#define NRELS    500
#define KDIM     272          // 266 real features padded to 17*16
#define KSTEPS   17
#define W1LD     1056         // 1044 padded to mult of 8 (pad zeroed)
#define NSAMP    5
#define JROWS    (NSAMP*256)  // 1280
#define BCCOLS   2560         // [B | C] stacked
#define W1SZ     (256*1044)

// ---------------- device scratch (static, no allocs) ----------------
__device__ float g_W1[JROWS * W1LD];                 // 5.4 MB sampled w1 (fp32, for cvec + A gemm)
__device__ __nv_bfloat16 g_Wh[BCCOLS * KDIM];        // 1.4 MB split-hi of stacked [B;C] weights
__device__ __nv_bfloat16 g_Wl[BCCOLS * KDIM];
__device__ __nv_bfloat16 g_hEh[(size_t)N_NODES * KDIM]; // 54.4 MB node features hi
__device__ __nv_bfloat16 g_hEl[(size_t)N_NODES * KDIM];
__device__ float g_b1[JROWS];
__device__ float g_w2[JROWS];
__device__ float g_b2[NSAMP];
__device__ float g_cvec[JROWS];
__device__ float g_A[NRELS * JROWS];                 // 2.56 MB relation part
__device__ float g_BC[(size_t)N_NODES * BCCOLS];     // 1.02 GB  [B | C]
__device__ float g_degT[N_NODES];
__device__ float g_degH[N_NODES];
__device__ float g_f1[N_NODES*2], g_f2[N_NODES*2];
__device__ float g_r1[N_NODES*2], g_r2[N_NODES*2];
__device__ int   g_is64;

// ---------------- index dtype shim ----------------
__global__ void k_detect(const unsigned int* p) {
    int nz = 0;
    for (int j = 1; j < 256; j += 2) nz |= (p[j] != 0u);
    g_is64 = nz ? 0 : 1;
}
__device__ __forceinline__ int getid(const void* p, int e) {
    if (g_is64) return (int)((const long long*)p)[e];
    return ((const int*)p)[e];
}

// ---------------- JAX threefry2x32 (partitionable semantics) ----------------
__device__ __forceinline__ unsigned rotl32(unsigned v, int r) {
    return (v << r) | (v >> (32 - r));
}
__device__ __forceinline__ void tf2x32(unsigned k0, unsigned k1,
                                       unsigned& x0, unsigned& x1) {
    unsigned ks0 = k0, ks1 = k1, ks2 = k0 ^ k1 ^ 0x1BD11BDAu;
    x0 += ks0; x1 += ks1;
    const int RA[4] = {13, 15, 26, 6};
    const int RB[4] = {17, 29, 16, 24};
    unsigned ks[3] = {ks0, ks1, ks2};
    #pragma unroll
    for (int i = 0; i < 5; i++) {
        const int* R = (i & 1) ? RB : RA;
        #pragma unroll
        for (int j = 0; j < 4; j++) {
            x0 += x1; x1 = rotl32(x1, R[j]); x1 ^= x0;
        }
        x0 += ks[(i + 1) % 3];
        x1 += ks[(i + 2) % 3] + (unsigned)(i + 1);
    }
}
__device__ __forceinline__ void sample_keys(int i, unsigned sk[4][2]) {
    unsigned a = 0u, b = (unsigned)i;
    tf2x32(0u, 42u, a, b);                       // fold_in
    #pragma unroll
    for (int m = 0; m < 4; m++) {
        unsigned x0 = 0u, x1 = (unsigned)m;
        tf2x32(a, b, x0, x1);
        sk[m][0] = x0; sk[m][1] = x1;
    }
}
__device__ __forceinline__ unsigned draw_bits(unsigned k0, unsigned k1, unsigned j) {
    unsigned x0 = 0u, x1 = j;
    tf2x32(k0, k1, x0, x1);
    return x0 ^ x1;
}
__device__ __forceinline__ float jax_normal(unsigned bits) {
    float f = __uint_as_float(0x3F800000u | (bits >> 9)) - 1.0f;
    const float lo = -0.99999994f;
    float u = f * 2.0f + lo;
    u = fmaxf(lo, u);
    return 1.4142135623730951f * erfinvf(u);
}
__device__ __forceinline__ float softplus_f(float x) {
    return fmaxf(x, 0.0f) + log1pf(expf(-fabsf(x)));
}

// ---------------- weight sampling (+ split-bf16 packing of [B;C] weights) ----------------
__global__ void k_gen_w1(const float* __restrict__ mu,
                         const float* __restrict__ rho) {
    int tid = blockIdx.x * blockDim.x + threadIdx.x;
    if (tid >= NSAMP * W1SZ) return;
    int i = tid / W1SZ, j = tid % W1SZ;
    unsigned sk[4][2]; sample_keys(i, sk);
    unsigned bits = draw_bits(sk[0][0], sk[0][1], (unsigned)j);
    float eps = jax_normal(bits);
    int row = j / 1044, k = j % 1044;
    float w = mu[j] + eps * softplus_f(rho[j]);
    int r = i * 256 + row;
    g_W1[(size_t)r * W1LD + k] = w;
    // split-bf16 copies into the stacked [B;C] weight planes
    int bcrow = -1, kk = 0;
    if (k >= 256 && k < 522)      { bcrow = r;          kk = k - 256; }
    else if (k >= 778)            { bcrow = 1280 + r;   kk = k - 778; }
    if (bcrow >= 0) {
        __nv_bfloat16 hi = __float2bfloat16(w);
        float lo = w - __bfloat162float(hi);
        size_t idx = (size_t)bcrow * KDIM + kk;
        g_Wh[idx] = hi;
        g_Wl[idx] = __float2bfloat16(lo);
    }
}
__global__ void k_gen_small(const float* __restrict__ b1mu, const float* __restrict__ b1rho,
                            const float* __restrict__ w2mu, const float* __restrict__ w2rho,
                            const float* __restrict__ b2mu, const float* __restrict__ b2rho) {
    int tid = blockIdx.x * blockDim.x + threadIdx.x;
    if (tid >= NSAMP * 513) return;
    int i = tid / 513, m = tid % 513;
    unsigned sk[4][2]; sample_keys(i, sk);
    if (m < 256) {
        unsigned bits = draw_bits(sk[1][0], sk[1][1], (unsigned)m);
        g_b1[i * 256 + m] = b1mu[m] + jax_normal(bits) * softplus_f(b1rho[m]);
    } else if (m < 512) {
        int j = m - 256;
        unsigned bits = draw_bits(sk[2][0], sk[2][1], (unsigned)j);
        g_w2[i * 256 + j] = w2mu[j] + jax_normal(bits) * softplus_f(w2rho[j]);
    } else {
        unsigned bits = draw_bits(sk[3][0], sk[3][1], 0u);
        g_b2[i] = b2mu[0] + jax_normal(bits) * softplus_f(b2rho[0]);
    }
}

// ---------------- zero scratch + weight pads ----------------
__global__ void k_zero() {
    int tid = blockIdx.x * blockDim.x + threadIdx.x;
    int stride = gridDim.x * blockDim.x;
    for (int i = tid; i < N_NODES; i += stride) { g_degT[i] = 0.f; g_degH[i] = 0.f; }
    for (int i = tid; i < N_NODES * 2; i += stride) {
        g_f1[i] = 0.f; g_f2[i] = 0.f; g_r1[i] = 0.f; g_r2[i] = 0.f;
    }
    // zero split-W pad cols 266..271 for all BCCOLS rows
    for (int i = tid; i < BCCOLS * 6; i += stride) {
        int rrow = i / 6, kk = 266 + i % 6;
        size_t idx = (size_t)rrow * KDIM + kk;
        g_Wh[idx] = __float2bfloat16(0.f);
        g_Wl[idx] = __float2bfloat16(0.f);
    }
    // zero W1 fp32 pad cols (1044..1055) for A-gemm/cvec safety
    for (int i = tid; i < JROWS * (W1LD - 1044); i += stride) {
        int j = i / (W1LD - 1044), k = 1044 + i % (W1LD - 1044);
        g_W1[(size_t)j * W1LD + k] = 0.f;
    }
}

// ---------------- DDE mean-conv ----------------
__global__ void k_deg(const void* hid, const void* tid_, int E) {
    int e = blockIdx.x * blockDim.x + threadIdx.x;
    if (e >= E) return;
    atomicAdd(&g_degT[getid(tid_, e)], 1.0f);
    atomicAdd(&g_degH[getid(hid, e)], 1.0f);
}
__global__ void k_scatter(const void* sids, const void* dids,
                          const float* __restrict__ xext, int xsel, int accsel, int E) {
    int e = blockIdx.x * blockDim.x + threadIdx.x;
    if (e >= E) return;
    const float* x = (xsel < 0) ? xext : (xsel == 0 ? g_f1 : g_r1);
    float* acc = (accsel == 0) ? g_f1 : (accsel == 1) ? g_f2
               : (accsel == 2) ? g_r1 : g_r2;
    int s = getid(sids, e), d = getid(dids, e);
    atomicAdd(&acc[2 * d],     x[2 * s]);
    atomicAdd(&acc[2 * d + 1], x[2 * s + 1]);
}
__global__ void k_div(int accsel, int degsel) {
    int v = blockIdx.x * blockDim.x + threadIdx.x;
    if (v >= N_NODES) return;
    float* acc = (accsel == 0) ? g_f1 : (accsel == 1) ? g_f2
               : (accsel == 2) ? g_r1 : g_r2;
    float d = fmaxf(degsel == 0 ? g_degT[v] : g_degH[v], 1.0f);
    acc[2 * v]     /= d;
    acc[2 * v + 1] /= d;
}

// ---------------- build node feature matrix (split bf16) ----------------
__global__ void k_pack(const float* __restrict__ ent, const float* __restrict__ nte,
                       const float* __restrict__ topic) {
    long long tid = (long long)blockIdx.x * blockDim.x + threadIdx.x;
    if (tid >= (long long)N_NODES * KDIM) return;
    int v = (int)(tid / KDIM), c = (int)(tid % KDIM);
    float val;
    if (c < 256)      val = (v < N_TEXT) ? ent[(size_t)v * 256 + c] : nte[c];
    else if (c < 258) val = topic[v * 2 + (c - 256)];
    else if (c < 260) val = g_f1[v * 2 + (c - 258)];
    else if (c < 262) val = g_f2[v * 2 + (c - 260)];
    else if (c < 264) val = g_r1[v * 2 + (c - 262)];
    else if (c < 266) val = g_r2[v * 2 + (c - 264)];
    else              val = 0.0f;
    __nv_bfloat16 hi = __float2bfloat16(val);
    float lo = val - __bfloat162float(hi);
    size_t idx = (size_t)v * KDIM + c;
    g_hEh[idx] = hi;
    g_hEl[idx] = __float2bfloat16(lo);
}

// ---------------- cvec = b1 + W1[:, :256] @ q ----------------
__global__ void k_cvec(const float* __restrict__ q) {
    int w = (blockIdx.x * blockDim.x + threadIdx.x) >> 5;
    int lane = threadIdx.x & 31;
    if (w >= JROWS) return;
    float s = 0.f;
    for (int k = lane; k < 256; k += 32) s += g_W1[(size_t)w * W1LD + k] * q[k];
    #pragma unroll
    for (int o = 16; o; o >>= 1) s += __shfl_xor_sync(0xFFFFFFFFu, s, o);
    if (!lane) g_cvec[w] = s + g_b1[w];
}

// ---------------- small fp32 SIMT GEMM: A = rel @ W1[:,522:778]^T ----------------
__global__ void __launch_bounds__(256)
k_agemm(const float* __restrict__ X) {
    __shared__ float As[8][128];
    __shared__ float Bs[8][128];
    const int M = NRELS, K = 256, off = 522;
    int m0 = blockIdx.y * 128, n0 = blockIdx.x * 128;
    int tid = threadIdx.x;
    int lr = tid >> 1, lk = (tid & 1) * 4;
    int tr = tid >> 4, tc = tid & 15;
    const float* Wp = g_W1 + (size_t)n0 * W1LD + off;

    float acc[8][8];
    #pragma unroll
    for (int i = 0; i < 8; i++)
        #pragma unroll
        for (int j = 0; j < 8; j++) acc[i][j] = 0.f;

    for (int k0 = 0; k0 < K; k0 += 8) {
        #pragma unroll
        for (int u = 0; u < 4; u++) {
            int m = m0 + lr;
            As[lk + u][lr] = (m < M) ? X[(size_t)m * 256 + k0 + lk + u] : 0.f;
            Bs[lk + u][lr] = Wp[(size_t)lr * W1LD + k0 + lk + u];
        }
        __syncthreads();
        #pragma unroll
        for (int kk = 0; kk < 8; kk++) {
            float4 a0 = *(const float4*)&As[kk][tr * 8];
            float4 a1 = *(const float4*)&As[kk][tr * 8 + 4];
            float4 b0 = *(const float4*)&Bs[kk][tc * 8];
            float4 b1 = *(const float4*)&Bs[kk][tc * 8 + 4];
            float a[8] = {a0.x, a0.y, a0.z, a0.w, a1.x, a1.y, a1.z, a1.w};
            float b[8] = {b0.x, b0.y, b0.z, b0.w, b1.x, b1.y, b1.z, b1.w};
            #pragma unroll
            for (int i = 0; i < 8; i++)
                #pragma unroll
                for (int j = 0; j < 8; j++) acc[i][j] += a[i] * b[j];
        }
        __syncthreads();
    }
    #pragma unroll
    for (int i = 0; i < 8; i++) {
        int m = m0 + tr * 8 + i;
        if (m < M) {
            float4* dst = (float4*)&g_A[(size_t)m * JROWS + n0 + tc * 8];
            dst[0] = make_float4(acc[i][0], acc[i][1], acc[i][2], acc[i][3]);
            dst[1] = make_float4(acc[i][4], acc[i][5], acc[i][6], acc[i][7]);
        }
    }
}

// ---------------- tensor-core MMA helpers ----------------
__device__ __forceinline__ void ldsm4(unsigned* r, unsigned addr) {
    asm volatile("ldmatrix.sync.aligned.m8n8.x4.shared.b16 {%0,%1,%2,%3}, [%4];"
        : "=r"(r[0]), "=r"(r[1]), "=r"(r[2]), "=r"(r[3]) : "r"(addr));
}
__device__ __forceinline__ void ldsm2(unsigned* r, unsigned addr) {
    asm volatile("ldmatrix.sync.aligned.m8n8.x2.shared.b16 {%0,%1}, [%2];"
        : "=r"(r[0]), "=r"(r[1]) : "r"(addr));
}
__device__ __forceinline__ void mma16816(float* c, const unsigned* a, const unsigned* b) {
    asm volatile("mma.sync.aligned.m16n8k16.row.col.f32.bf16.bf16.f32 "
        "{%0,%1,%2,%3}, {%4,%5,%6,%7}, {%8,%9}, {%0,%1,%2,%3};"
        : "+f"(c[0]), "+f"(c[1]), "+f"(c[2]), "+f"(c[3])
        : "r"(a[0]), "r"(a[1]), "r"(a[2]), "r"(a[3]), "r"(b[0]), "r"(b[1]));
}

// ---------------- BC tensor-core GEMM: g_BC[M,2560] = hE @ W_BC^T (split bf16, 3-MMA) --------
// Block 128(M) x 128(N), 8 warps as 4(M) x 2(N) -> warp tile 32x64.
__global__ void __launch_bounds__(256, 1)
k_bcmma() {
    __shared__ __align__(16) __nv_bfloat16 As[2][2][128][24]; // [stage][plane][m][kpad]
    __shared__ __align__(16) __nv_bfloat16 Bs[2][2][128][24];

    const int M = N_NODES;
    int tid = threadIdx.x;
    int lane = tid & 31, warp = tid >> 5;
    int wm = warp & 3, wn = warp >> 2;
    int m0 = blockIdx.y * 128, n0 = blockIdx.x * 128;

    float acc[2][8][4];
    #pragma unroll
    for (int mi = 0; mi < 2; mi++)
        #pragma unroll
        for (int ni = 0; ni < 8; ni++)
            #pragma unroll
            for (int c = 0; c < 4; c++) acc[mi][ni][c] = 0.f;

    uint4 ra[2], rb[2];
    // decode per-thread load slots: flat = tid + 256*i ; slot: row(128) x plane(2) x half(2)
    int rowS[2], plS[2], hfS[2];
    #pragma unroll
    for (int i = 0; i < 2; i++) {
        int flat = tid + 256 * i;
        rowS[i] = flat >> 2; plS[i] = (flat >> 1) & 1; hfS[i] = flat & 1;
    }

    #define LOADG(ks)                                                              \
        _Pragma("unroll")                                                          \
        for (int i = 0; i < 2; i++) {                                              \
            int m = m0 + rowS[i];                                                  \
            size_t goff = (size_t)m * KDIM + (ks) * 16 + hfS[i] * 8;               \
            if (m < M)                                                             \
                ra[i] = *(const uint4*)((plS[i] ? g_hEl : g_hEh) + goff);          \
            else ra[i] = make_uint4(0u, 0u, 0u, 0u);                               \
            size_t woff = (size_t)(n0 + rowS[i]) * KDIM + (ks) * 16 + hfS[i] * 8;  \
            rb[i] = *(const uint4*)((plS[i] ? g_Wl : g_Wh) + woff);                \
        }
    #define STORES(st)                                                             \
        _Pragma("unroll")                                                          \
        for (int i = 0; i < 2; i++) {                                              \
            *(uint4*)&As[st][plS[i]][rowS[i]][hfS[i] * 8] = ra[i];                 \
            *(uint4*)&Bs[st][plS[i]][rowS[i]][hfS[i] * 8] = rb[i];                 \
        }

    LOADG(0);
    STORES(0);

    int arow = wm * 32 + (lane & 15);
    int akf  = (lane >> 4) * 8;
    int brow0 = wn * 64 + (lane & 7);
    int bkf  = ((lane >> 3) & 1) * 8;

    for (int ks = 0; ks < KSTEPS; ks++) {
        int st = ks & 1;
        __syncthreads();
        if (ks + 1 < KSTEPS) { LOADG(ks + 1); }

        unsigned aH[2][4], aL[2][4];
        #pragma unroll
        for (int mi = 0; mi < 2; mi++) {
            ldsm4(aH[mi], (unsigned)__cvta_generic_to_shared(&As[st][0][arow + mi * 16][akf]));
            ldsm4(aL[mi], (unsigned)__cvta_generic_to_shared(&As[st][1][arow + mi * 16][akf]));
        }
        #pragma unroll
        for (int ni = 0; ni < 8; ni++) {
            unsigned bH[2], bL[2];
            ldsm2(bH, (unsigned)__cvta_generic_to_shared(&Bs[st][0][brow0 + ni * 8][bkf]));
            ldsm2(bL, (unsigned)__cvta_generic_to_shared(&Bs[st][1][brow0 + ni * 8][bkf]));
            #pragma unroll
            for (int mi = 0; mi < 2; mi++) {
                mma16816(acc[mi][ni], aH[mi], bH);
                mma16816(acc[mi][ni], aL[mi], bH);
                mma16816(acc[mi][ni], aH[mi], bL);
            }
        }
        if (ks + 1 < KSTEPS) { STORES((ks + 1) & 1); }
    }
    #undef LOADG
    #undef STORES

    // epilogue
    int g = lane >> 2, tg = lane & 3;
    #pragma unroll
    for (int mi = 0; mi < 2; mi++) {
        #pragma unroll
        for (int ni = 0; ni < 8; ni++) {
            int row = m0 + wm * 32 + mi * 16 + g;
            int col = n0 + wn * 64 + ni * 8 + tg * 2;
            if (row < M)
                *(float2*)&g_BC[(size_t)row * BCCOLS + col] =
                    make_float2(acc[mi][ni][0], acc[mi][ni][1]);
            if (row + 8 < M)
                *(float2*)&g_BC[(size_t)(row + 8) * BCCOLS + col] =
                    make_float2(acc[mi][ni][2], acc[mi][ni][3]);
        }
    }
}

// ---------------- per-edge: gather + relu + dot(w2), mean over samples ----------------
__global__ void __launch_bounds__(256)
k_edge(const void* hid, const void* rid, const void* tid_,
       float* __restrict__ out, int E) {
    int gw = (blockIdx.x * blockDim.x + threadIdx.x) >> 5;
    int lane = threadIdx.x & 31;
    if (gw >= E) return;
    int h = getid(hid, gw), t = getid(tid_, gw), r = getid(rid, gw);
    const float4* Bp = (const float4*)(g_BC + (size_t)h * BCCOLS);
    const float4* Cp = (const float4*)(g_BC + (size_t)t * BCCOLS + JROWS);
    const float4* Ap = (const float4*)(g_A + (size_t)r * JROWS);
    const float4* cp = (const float4*)g_cvec;
    const float4* wp = (const float4*)g_w2;
    float acc = 0.f;
    #pragma unroll
    for (int it = 0; it < 10; it++) {
        int idx = it * 32 + lane;
        float4 b = Bp[idx], c = Cp[idx], a = Ap[idx], cc = cp[idx], w = wp[idx];
        acc += fmaxf(b.x + c.x + a.x + cc.x, 0.f) * w.x;
        acc += fmaxf(b.y + c.y + a.y + cc.y, 0.f) * w.y;
        acc += fmaxf(b.z + c.z + a.z + cc.z, 0.f) * w.z;
        acc += fmaxf(b.w + c.w + a.w + cc.w, 0.f) * w.w;
    }
    #pragma unroll
    for (int o = 16; o; o >>= 1) acc += __shfl_xor_sync(0xFFFFFFFFu, acc, o);
    if (!lane) {
        float b2s = g_b2[0] + g_b2[1] + g_b2[2] + g_b2[3] + g_b2[4];
        out[gw] = (acc + b2s) / 5.0f;
    }
}

// ---------------- host launch ----------------
extern "C" void kernel_launch(void* const* d_in, const int* in_sizes, int n_in,
                              void* d_out, int out_size) {
    int base = (n_in >= 7 && in_sizes[5] == 1) ? 1 : 0;
    const void*  hid   = d_in[0];
    const void*  rid   = d_in[1];
    const void*  tidp  = d_in[2];
    const float* q     = (const float*)d_in[3];
    const float* ent   = (const float*)d_in[4];
    const float* rel   = (const float*)d_in[5 + base];
    const float* topic = (const float*)d_in[6 + base];
    const float* nte   = (const float*)d_in[7 + base];
    const float* w1mu  = (const float*)d_in[8 + base];
    const float* w1rho = (const float*)d_in[9 + base];
    const float* b1mu  = (const float*)d_in[10 + base];
    const float* b1rho = (const float*)d_in[11 + base];
    const float* w2mu  = (const float*)d_in[12 + base];
    const float* w2rho = (const float*)d_in[13 + base];
    const float* b2mu  = (const float*)d_in[14 + base];
    const float* b2rho = (const float*)d_in[15 + base];
    int E = in_sizes[0];
    float* out = (float*)d_out;

    k_detect<<<1, 1>>>((const unsigned int*)hid);
    k_zero<<<1024, 256>>>();
    k_gen_w1<<<(NSAMP * W1SZ + 255) / 256, 256>>>(w1mu, w1rho);
    k_gen_small<<<(NSAMP * 513 + 255) / 256, 256>>>(b1mu, b1rho, w2mu, w2rho, b2mu, b2rho);

    int eb = (E + 255) / 256;
    k_deg<<<eb, 256>>>(hid, tidp, E);
    k_scatter<<<eb, 256>>>(hid, tidp, topic, -1, 0, E);
    k_div<<<(N_NODES + 255) / 256, 256>>>(0, 0);
    k_scatter<<<eb, 256>>>(hid, tidp, nullptr, 0, 1, E);
    k_div<<<(N_NODES + 255) / 256, 256>>>(1, 0);
    k_scatter<<<eb, 256>>>(tidp, hid, topic, -1, 2, E);
    k_div<<<(N_NODES + 255) / 256, 256>>>(2, 1);
    k_scatter<<<eb, 256>>>(tidp, hid, nullptr, 1, 3, E);
    k_div<<<(N_NODES + 255) / 256, 256>>>(3, 1);

    long long packN = (long long)N_NODES * KDIM;
    k_pack<<<(unsigned)((packN + 255) / 256), 256>>>(ent, nte, topic);
    k_cvec<<<(JROWS * 32) / 256, 256>>>(q);

    k_agemm<<<dim3(10, (NRELS + 127) / 128), 256>>>(rel);
    k_bcmma<<<dim3(BCCOLS / 128, (N_NODES + 127) / 128), 256>>>();

    long long tot = (long long)E * 32;
    k_edge<<<(unsigned)((tot + 255) / 256), 256>>>(hid, rid, tidp, out, E);
}

// round 5
// speedup vs baseline: 4.3045x; 2.1590x over previous
#include <cuda_runtime.h>
#include <cuda_fp16.h>
#include <cstdint>
#include <cstddef>

// ---------------- problem constants ----------------
#define N_TEXT   90000
#define N_NODES  100000
#define NRELS    500
#define KD       272              // 266 features padded to 17*16
#define KSTEPS   17
#define MTILES   782              // ceil(100000/128)
#define MROWS    (MTILES*128)     // 100096
#define W1LD     1056
#define NSAMP    5
#define JROWS    (NSAMP*256)      // 1280
#define BCCOLS   2560
#define W1SZ     (256*1044)

// ---------------- device scratch (static, no allocs) ----------------
__device__ float  g_W1[JROWS * W1LD];                 // fp32 sampled w1 (cvec + A gemm)
__device__ __half g_hEf[(size_t)MROWS * KD];          // 54.5MB node features fp16
__device__ __half g_Wf[(size_t)BCCOLS * KD];          // 1.4MB stacked [B;C] weights fp16
__device__ __half g_BCh[(size_t)N_NODES * BCCOLS];    // 512MB [B|C] fp16
__device__ __half g_Ah[NRELS * JROWS];                // 1.28MB  A' = rel-part + cvec, fp16
__device__ float  g_b1[JROWS];
__device__ float  g_w2[JROWS];
__device__ float  g_b2[NSAMP];
__device__ float  g_cvec[JROWS];
__device__ float  g_degT[N_NODES];
__device__ float  g_degH[N_NODES];
__device__ float  g_f1[N_NODES*2], g_f2[N_NODES*2];
__device__ float  g_r1[N_NODES*2], g_r2[N_NODES*2];
__device__ int    g_is64;

// ---------------- index dtype shim ----------------
__global__ void k_detect(const unsigned int* p) {
    int nz = 0;
    for (int j = 1; j < 256; j += 2) nz |= (p[j] != 0u);
    g_is64 = nz ? 0 : 1;
}
__device__ __forceinline__ int getid(const void* p, int e) {
    if (g_is64) return (int)((const long long*)p)[e];
    return ((const int*)p)[e];
}

// ---------------- JAX threefry2x32 (partitionable) ----------------
__device__ __forceinline__ unsigned rotl32(unsigned v, int r) {
    return (v << r) | (v >> (32 - r));
}
__device__ __forceinline__ void tf2x32(unsigned k0, unsigned k1,
                                       unsigned& x0, unsigned& x1) {
    unsigned ks0 = k0, ks1 = k1, ks2 = k0 ^ k1 ^ 0x1BD11BDAu;
    x0 += ks0; x1 += ks1;
    const int RA[4] = {13, 15, 26, 6};
    const int RB[4] = {17, 29, 16, 24};
    unsigned ks[3] = {ks0, ks1, ks2};
    #pragma unroll
    for (int i = 0; i < 5; i++) {
        const int* R = (i & 1) ? RB : RA;
        #pragma unroll
        for (int j = 0; j < 4; j++) {
            x0 += x1; x1 = rotl32(x1, R[j]); x1 ^= x0;
        }
        x0 += ks[(i + 1) % 3];
        x1 += ks[(i + 2) % 3] + (unsigned)(i + 1);
    }
}
__device__ __forceinline__ void sample_keys(int i, unsigned sk[4][2]) {
    unsigned a = 0u, b = (unsigned)i;
    tf2x32(0u, 42u, a, b);
    #pragma unroll
    for (int m = 0; m < 4; m++) {
        unsigned x0 = 0u, x1 = (unsigned)m;
        tf2x32(a, b, x0, x1);
        sk[m][0] = x0; sk[m][1] = x1;
    }
}
__device__ __forceinline__ unsigned draw_bits(unsigned k0, unsigned k1, unsigned j) {
    unsigned x0 = 0u, x1 = j;
    tf2x32(k0, k1, x0, x1);
    return x0 ^ x1;
}
__device__ __forceinline__ float jax_normal(unsigned bits) {
    float f = __uint_as_float(0x3F800000u | (bits >> 9)) - 1.0f;
    const float lo = -0.99999994f;
    float u = f * 2.0f + lo;
    u = fmaxf(lo, u);
    return 1.4142135623730951f * erfinvf(u);
}
__device__ __forceinline__ float softplus_f(float x) {
    return fmaxf(x, 0.0f) + log1pf(expf(-fabsf(x)));
}

// ---------------- weight sampling ----------------
__global__ void k_gen_w1(const float* __restrict__ mu,
                         const float* __restrict__ rho) {
    int tid = blockIdx.x * blockDim.x + threadIdx.x;
    if (tid >= NSAMP * W1SZ) return;
    int i = tid / W1SZ, j = tid % W1SZ;
    unsigned sk[4][2]; sample_keys(i, sk);
    unsigned bits = draw_bits(sk[0][0], sk[0][1], (unsigned)j);
    float eps = jax_normal(bits);
    int row = j / 1044, k = j % 1044;
    float w = mu[j] + eps * softplus_f(rho[j]);
    int r = i * 256 + row;
    g_W1[(size_t)r * W1LD + k] = w;
    int bcrow = -1, kk = 0;
    if (k >= 256 && k < 522)      { bcrow = r;        kk = k - 256; }
    else if (k >= 778)            { bcrow = 1280 + r; kk = k - 778; }
    if (bcrow >= 0)
        g_Wf[(size_t)bcrow * KD + kk] = __float2half_rn(w);
}
__global__ void k_gen_small(const float* __restrict__ b1mu, const float* __restrict__ b1rho,
                            const float* __restrict__ w2mu, const float* __restrict__ w2rho,
                            const float* __restrict__ b2mu, const float* __restrict__ b2rho) {
    int tid = blockIdx.x * blockDim.x + threadIdx.x;
    if (tid >= NSAMP * 513) return;
    int i = tid / 513, m = tid % 513;
    unsigned sk[4][2]; sample_keys(i, sk);
    if (m < 256) {
        unsigned bits = draw_bits(sk[1][0], sk[1][1], (unsigned)m);
        g_b1[i * 256 + m] = b1mu[m] + jax_normal(bits) * softplus_f(b1rho[m]);
    } else if (m < 512) {
        int j = m - 256;
        unsigned bits = draw_bits(sk[2][0], sk[2][1], (unsigned)j);
        g_w2[i * 256 + j] = w2mu[j] + jax_normal(bits) * softplus_f(w2rho[j]);
    } else {
        unsigned bits = draw_bits(sk[3][0], sk[3][1], 0u);
        g_b2[i] = b2mu[0] + jax_normal(bits) * softplus_f(b2rho[0]);
    }
}

// ---------------- zero scratch + W pads ----------------
__global__ void k_zero() {
    int tid = blockIdx.x * blockDim.x + threadIdx.x;
    int stride = gridDim.x * blockDim.x;
    for (int i = tid; i < N_NODES; i += stride) { g_degT[i] = 0.f; g_degH[i] = 0.f; }
    for (int i = tid; i < N_NODES * 2; i += stride) {
        g_f1[i] = 0.f; g_f2[i] = 0.f; g_r1[i] = 0.f; g_r2[i] = 0.f;
    }
    // zero W pad cols 266..271 (so K-pad contributes exactly 0 regardless of hE pad)
    for (int i = tid; i < BCCOLS * (KD - 266); i += stride) {
        int rr = i / (KD - 266), kk = 266 + i % (KD - 266);
        g_Wf[(size_t)rr * KD + kk] = __float2half_rn(0.f);
    }
}

// ---------------- fused DDE mean-conv ----------------
// round 1 both directions + degrees
__global__ void k_scat1(const void* hid, const void* tid_,
                        const float* __restrict__ topic, int E) {
    int e = blockIdx.x * blockDim.x + threadIdx.x;
    if (e >= E) return;
    int h = getid(hid, e), t = getid(tid_, e);
    float2 xh = *(const float2*)&topic[2 * h];
    float2 xt = *(const float2*)&topic[2 * t];
    atomicAdd(&g_f1[2 * t],     xh.x);
    atomicAdd(&g_f1[2 * t + 1], xh.y);
    atomicAdd(&g_r1[2 * h],     xt.x);
    atomicAdd(&g_r1[2 * h + 1], xt.y);
    atomicAdd(&g_degT[t], 1.0f);
    atomicAdd(&g_degH[h], 1.0f);
}
__global__ void k_div1() {
    int v = blockIdx.x * blockDim.x + threadIdx.x;
    if (v >= N_NODES) return;
    float dt = fmaxf(g_degT[v], 1.0f), dh = fmaxf(g_degH[v], 1.0f);
    g_f1[2 * v] /= dt; g_f1[2 * v + 1] /= dt;
    g_r1[2 * v] /= dh; g_r1[2 * v + 1] /= dh;
}
__global__ void k_scat2(const void* hid, const void* tid_, int E) {
    int e = blockIdx.x * blockDim.x + threadIdx.x;
    if (e >= E) return;
    int h = getid(hid, e), t = getid(tid_, e);
    float2 xh = *(const float2*)&g_f1[2 * h];
    float2 xt = *(const float2*)&g_r1[2 * t];
    atomicAdd(&g_f2[2 * t],     xh.x);
    atomicAdd(&g_f2[2 * t + 1], xh.y);
    atomicAdd(&g_r2[2 * h],     xt.x);
    atomicAdd(&g_r2[2 * h + 1], xt.y);
}
__global__ void k_div2() {
    int v = blockIdx.x * blockDim.x + threadIdx.x;
    if (v >= N_NODES) return;
    float dt = fmaxf(g_degT[v], 1.0f), dh = fmaxf(g_degH[v], 1.0f);
    g_f2[2 * v] /= dt; g_f2[2 * v + 1] /= dt;
    g_r2[2 * v] /= dh; g_r2[2 * v + 1] /= dh;
}

// ---------------- build node features (fp16, K padded) ----------------
__global__ void k_pack(const float* __restrict__ ent, const float* __restrict__ nte,
                       const float* __restrict__ topic) {
    long long tid = (long long)blockIdx.x * blockDim.x + threadIdx.x;
    if (tid >= (long long)N_NODES * KD) return;
    int v = (int)(tid / KD), c = (int)(tid % KD);
    float val = 0.f;
    if (c < 256)      val = (v < N_TEXT) ? ent[(size_t)v * 256 + c] : nte[c];
    else if (c < 258) val = topic[v * 2 + (c - 256)];
    else if (c < 260) val = g_f1[v * 2 + (c - 258)];
    else if (c < 262) val = g_f2[v * 2 + (c - 260)];
    else if (c < 264) val = g_r1[v * 2 + (c - 262)];
    else if (c < 266) val = g_r2[v * 2 + (c - 264)];
    g_hEf[(size_t)v * KD + c] = __float2half_rn(val);
}

// ---------------- cvec = b1 + W1[:, :256] @ q ----------------
__global__ void k_cvec(const float* __restrict__ q) {
    int w = (blockIdx.x * blockDim.x + threadIdx.x) >> 5;
    int lane = threadIdx.x & 31;
    if (w >= JROWS) return;
    float s = 0.f;
    for (int k = lane; k < 256; k += 32) s += g_W1[(size_t)w * W1LD + k] * q[k];
    #pragma unroll
    for (int o = 16; o; o >>= 1) s += __shfl_xor_sync(0xFFFFFFFFu, s, o);
    if (!lane) g_cvec[w] = s + g_b1[w];
}

// ---------------- fp32 SIMT GEMM: A' = rel @ W1[:,522:778]^T + cvec (fp16 out) -------
__global__ void __launch_bounds__(256)
k_agemm(const float* __restrict__ X) {
    __shared__ float As[8][128];
    __shared__ float Bs[8][128];
    const int M = NRELS, K = 256, off = 522;
    int m0 = blockIdx.y * 128, n0 = blockIdx.x * 128;
    int tid = threadIdx.x;
    int lr = tid >> 1, lk = (tid & 1) * 4;
    int tr = tid >> 4, tc = tid & 15;
    const float* Wp = g_W1 + (size_t)n0 * W1LD + off;

    float acc[8][8];
    #pragma unroll
    for (int i = 0; i < 8; i++)
        #pragma unroll
        for (int j = 0; j < 8; j++) acc[i][j] = 0.f;

    for (int k0 = 0; k0 < K; k0 += 8) {
        #pragma unroll
        for (int u = 0; u < 4; u++) {
            int m = m0 + lr;
            As[lk + u][lr] = (m < M) ? X[(size_t)m * 256 + k0 + lk + u] : 0.f;
            Bs[lk + u][lr] = Wp[(size_t)lr * W1LD + k0 + lk + u];
        }
        __syncthreads();
        #pragma unroll
        for (int kk = 0; kk < 8; kk++) {
            float4 a0 = *(const float4*)&As[kk][tr * 8];
            float4 a1 = *(const float4*)&As[kk][tr * 8 + 4];
            float4 b0 = *(const float4*)&Bs[kk][tc * 8];
            float4 b1 = *(const float4*)&Bs[kk][tc * 8 + 4];
            float a[8] = {a0.x, a0.y, a0.z, a0.w, a1.x, a1.y, a1.z, a1.w};
            float b[8] = {b0.x, b0.y, b0.z, b0.w, b1.x, b1.y, b1.z, b1.w};
            #pragma unroll
            for (int i = 0; i < 8; i++)
                #pragma unroll
                for (int j = 0; j < 8; j++) acc[i][j] += a[i] * b[j];
        }
        __syncthreads();
    }
    #pragma unroll
    for (int i = 0; i < 8; i++) {
        int m = m0 + tr * 8 + i;
        if (m < M) {
            int col = n0 + tc * 8;
            __align__(16) __half hv[8];
            #pragma unroll
            for (int j = 0; j < 8; j++)
                hv[j] = __float2half_rn(acc[i][j] + g_cvec[col + j]);
            *(uint4*)&g_Ah[(size_t)m * JROWS + col] = *(uint4*)hv;
        }
    }
}

// ---------------- mma.sync helpers ----------------
__device__ __forceinline__ void ldsm4(unsigned* r, const void* p) {
    unsigned addr = (unsigned)__cvta_generic_to_shared(p);
    asm volatile("ldmatrix.sync.aligned.m8n8.x4.shared.b16 {%0,%1,%2,%3}, [%4];"
        : "=r"(r[0]), "=r"(r[1]), "=r"(r[2]), "=r"(r[3]) : "r"(addr));
}
__device__ __forceinline__ void ldsm2(unsigned* r, const void* p) {
    unsigned addr = (unsigned)__cvta_generic_to_shared(p);
    asm volatile("ldmatrix.sync.aligned.m8n8.x2.shared.b16 {%0,%1}, [%2];"
        : "=r"(r[0]), "=r"(r[1]) : "r"(addr));
}
__device__ __forceinline__ void mma16816(float* c, const unsigned* a, const unsigned* b) {
    asm volatile("mma.sync.aligned.m16n8k16.row.col.f32.f16.f16.f32 "
        "{%0,%1,%2,%3}, {%4,%5,%6,%7}, {%8,%9}, {%0,%1,%2,%3};"
        : "+f"(c[0]), "+f"(c[1]), "+f"(c[2]), "+f"(c[3])
        : "r"(a[0]), "r"(a[1]), "r"(a[2]), "r"(a[3]), "r"(b[0]), "r"(b[1]));
}

// ---------------- BC GEMM (fp16 single-plane): g_BCh = hE @ W^T -----------------------
// Block 128(M) x 128(N), 8 warps 4x2, warp tile 32x64, K=272 in 17 steps of 16.
__global__ void __launch_bounds__(256)
k_bcmma() {
    __shared__ __align__(16) __half As[2][128][24];
    __shared__ __align__(16) __half Bs[2][128][24];

    int tid = threadIdx.x, lane = tid & 31, warp = tid >> 5;
    int wm = warp & 3, wn = warp >> 2;
    int m0 = blockIdx.y * 128, n0 = blockIdx.x * 128;

    float acc[2][8][4];
    #pragma unroll
    for (int mi = 0; mi < 2; mi++)
        #pragma unroll
        for (int ni = 0; ni < 8; ni++)
            #pragma unroll
            for (int c = 0; c < 4; c++) acc[mi][ni][c] = 0.f;

    int rowL = tid >> 1, hf = tid & 1;
    const __half* Ag = g_hEf + (size_t)(m0 + rowL) * KD + hf * 8;  // rows < MROWS always
    const __half* Bg = g_Wf  + (size_t)(n0 + rowL) * KD + hf * 8;

    uint4 ra = *(const uint4*)Ag;
    uint4 rb = *(const uint4*)Bg;
    *(uint4*)&As[0][rowL][hf * 8] = ra;
    *(uint4*)&Bs[0][rowL][hf * 8] = rb;

    int arow = wm * 32 + (lane & 15);
    int akf  = (lane >> 4) * 8;
    int brow = wn * 64 + (lane & 7);
    int bkf  = ((lane >> 3) & 1) * 8;

    for (int ks = 0; ks < KSTEPS; ks++) {
        int st = ks & 1;
        __syncthreads();
        if (ks + 1 < KSTEPS) {
            ra = *(const uint4*)(Ag + (size_t)(ks + 1) * 16);
            rb = *(const uint4*)(Bg + (size_t)(ks + 1) * 16);
        }
        unsigned a[2][4];
        ldsm4(a[0], &As[st][arow][akf]);
        ldsm4(a[1], &As[st][arow + 16][akf]);
        #pragma unroll
        for (int ni = 0; ni < 8; ni++) {
            unsigned b[2];
            ldsm2(b, &Bs[st][brow + ni * 8][bkf]);
            mma16816(acc[0][ni], a[0], b);
            mma16816(acc[1][ni], a[1], b);
        }
        if (ks + 1 < KSTEPS) {
            *(uint4*)&As[st ^ 1][rowL][hf * 8] = ra;
            *(uint4*)&Bs[st ^ 1][rowL][hf * 8] = rb;
        }
    }

    // epilogue -> fp16
    int g = lane >> 2, tg = lane & 3;
    #pragma unroll
    for (int mi = 0; mi < 2; mi++) {
        #pragma unroll
        for (int ni = 0; ni < 8; ni++) {
            int row = m0 + wm * 32 + mi * 16 + g;
            int col = n0 + wn * 64 + ni * 8 + tg * 2;
            if (row < N_NODES)
                *(__half2*)&g_BCh[(size_t)row * BCCOLS + col] =
                    __floats2half2_rn(acc[mi][ni][0], acc[mi][ni][1]);
            if (row + 8 < N_NODES)
                *(__half2*)&g_BCh[(size_t)(row + 8) * BCCOLS + col] =
                    __floats2half2_rn(acc[mi][ni][2], acc[mi][ni][3]);
        }
    }
}

// ---------------- per-edge: gather + relu + dot(w2), mean over samples ----------------
__global__ void __launch_bounds__(256)
k_edge(const void* hid, const void* rid, const void* tid_,
       float* __restrict__ out, int E) {
    int gw = (blockIdx.x * blockDim.x + threadIdx.x) >> 5;
    int lane = threadIdx.x & 31;
    if (gw >= E) return;
    int h = getid(hid, gw), t = getid(tid_, gw), r = getid(rid, gw);
    const uint4* Bp = (const uint4*)(g_BCh + (size_t)h * BCCOLS);
    const uint4* Cp = (const uint4*)(g_BCh + (size_t)t * BCCOLS + JROWS);
    const uint4* Ap = (const uint4*)(g_Ah + (size_t)r * JROWS);
    const float4* wp = (const float4*)g_w2;
    float acc = 0.f;
    #pragma unroll
    for (int it = 0; it < 5; it++) {
        int idx = it * 32 + lane;             // uint4 = 8 halfs
        uint4 bv = Bp[idx], cv = Cp[idx], av = Ap[idx];
        float4 w0 = wp[2 * idx], w1 = wp[2 * idx + 1];
        const __half2* bh = (const __half2*)&bv;
        const __half2* chh = (const __half2*)&cv;
        const __half2* ah = (const __half2*)&av;
        float wv[8] = {w0.x, w0.y, w0.z, w0.w, w1.x, w1.y, w1.z, w1.w};
        #pragma unroll
        for (int j = 0; j < 4; j++) {
            float2 b = __half22float2(bh[j]);
            float2 c = __half22float2(chh[j]);
            float2 a = __half22float2(ah[j]);
            acc += fmaxf(b.x + c.x + a.x, 0.f) * wv[2 * j];
            acc += fmaxf(b.y + c.y + a.y, 0.f) * wv[2 * j + 1];
        }
    }
    #pragma unroll
    for (int o = 16; o; o >>= 1) acc += __shfl_xor_sync(0xFFFFFFFFu, acc, o);
    if (!lane) {
        float b2s = g_b2[0] + g_b2[1] + g_b2[2] + g_b2[3] + g_b2[4];
        out[gw] = (acc + b2s) / 5.0f;
    }
}

// ---------------- host launch ----------------
extern "C" void kernel_launch(void* const* d_in, const int* in_sizes, int n_in,
                              void* d_out, int out_size) {
    int base = (n_in >= 7 && in_sizes[5] == 1) ? 1 : 0;
    const void*  hid   = d_in[0];
    const void*  rid   = d_in[1];
    const void*  tidp  = d_in[2];
    const float* q     = (const float*)d_in[3];
    const float* ent   = (const float*)d_in[4];
    const float* rel   = (const float*)d_in[5 + base];
    const float* topic = (const float*)d_in[6 + base];
    const float* nte   = (const float*)d_in[7 + base];
    const float* w1mu  = (const float*)d_in[8 + base];
    const float* w1rho = (const float*)d_in[9 + base];
    const float* b1mu  = (const float*)d_in[10 + base];
    const float* b1rho = (const float*)d_in[11 + base];
    const float* w2mu  = (const float*)d_in[12 + base];
    const float* w2rho = (const float*)d_in[13 + base];
    const float* b2mu  = (const float*)d_in[14 + base];
    const float* b2rho = (const float*)d_in[15 + base];
    int E = in_sizes[0];
    float* out = (float*)d_out;

    k_detect<<<1, 1>>>((const unsigned int*)hid);
    k_zero<<<512, 256>>>();
    k_gen_w1<<<(NSAMP * W1SZ + 255) / 256, 256>>>(w1mu, w1rho);
    k_gen_small<<<(NSAMP * 513 + 255) / 256, 256>>>(b1mu, b1rho, w2mu, w2rho, b2mu, b2rho);

    int eb = (E + 255) / 256;
    k_scat1<<<eb, 256>>>(hid, tidp, topic, E);
    k_div1<<<(N_NODES + 255) / 256, 256>>>();
    k_scat2<<<eb, 256>>>(hid, tidp, E);
    k_div2<<<(N_NODES + 255) / 256, 256>>>();

    long long packN = (long long)N_NODES * KD;
    k_pack<<<(unsigned)((packN + 255) / 256), 256>>>(ent, nte, topic);
    k_cvec<<<(JROWS * 32) / 256, 256>>>(q);

    k_agemm<<<dim3(10, (NRELS + 127) / 128), 256>>>(rel);
    k_bcmma<<<dim3(BCCOLS / 128, MTILES), 256>>>();

    long long tot = (long long)E * 32;
    k_edge<<<(unsigned)((tot + 255) / 256), 256>>>(hid, rid, tidp, out, E);
}